// round 16
// baseline (speedup 1.0000x reference)
// R16: champion (R7/R14 P=16 independent warps, depth-2 B prefetch)
//      at 416 threads / 13 warps (reg cap ~156 > ~125 working set).
#include <cuda_runtime.h>
#include <cuda_fp16.h>
#include <cstdint>

// ============================================================================
// Constants
// ============================================================================
#define NSM       148
#define THREADS   416
#define WARPS     13
#define GRID3     262144        // 64^3
#define DIN       52

// SMEM byte offsets
#define OFF_W0    0             // 128 rows * 128B                 = 16384
#define OFF_WH    16384         // 3 * (128 rows * 256B) = 98304   -> 114688
#define OFF_STAGE 114688        // 13 warps * 2048B                -> 141312
#define OFF_BH    141312        // 3*128 f32 = 1536                -> 142848
#define OFF_WOUT  142848        // 128 f32 = 512                   -> 143360
#define OFF_BOUT  143360        // 1 f32
#define SMEM_TOTAL 143364

// fp16 feature grid, transposed: [64^3 voxels][16 channels]
__device__ __half g_gridT[(size_t)GRID3 * 16];

// ============================================================================
// Helpers (sm_80-era instructions only; PTX target is plain sm_100)
// ============================================================================
__device__ __forceinline__ uint32_t smem_u32(const void* p) {
    uint32_t a;
    asm("{ .reg .u64 t; cvta.to.shared.u64 t, %1; cvt.u32.u64 %0, t; }"
        : "=r"(a) : "l"(p));
    return a;
}

__device__ __forceinline__ void ldsm4(uint32_t* r, uint32_t addr) {
    asm volatile("ldmatrix.sync.aligned.m8n8.x4.shared.b16 {%0,%1,%2,%3},[%4];"
                 : "=r"(r[0]), "=r"(r[1]), "=r"(r[2]), "=r"(r[3]) : "r"(addr));
}

__device__ __forceinline__ void mma16816(float* c, const uint32_t* a,
                                         uint32_t b0, uint32_t b1) {
    asm volatile(
        "mma.sync.aligned.m16n8k16.row.col.f32.f16.f16.f32 "
        "{%0,%1,%2,%3},{%4,%5,%6,%7},{%8,%9},{%0,%1,%2,%3};"
        : "+f"(c[0]), "+f"(c[1]), "+f"(c[2]), "+f"(c[3])
        : "r"(a[0]), "r"(a[1]), "r"(a[2]), "r"(a[3]), "r"(b0), "r"(b1));
}

__device__ __forceinline__ uint32_t pack_h2(float lo, float hi) {
    uint32_t r;
    asm("cvt.rn.f16x2.f32 %0, %1, %2;" : "=r"(r) : "f"(hi), "f"(lo));
    return r;
}

// Weights/biases of snake layers pre-scaled by 2, so GEMM emits u = 2v
// exactly; snake(v) = 0.25u + 0.5 - 0.5*cos(u).
__device__ __forceinline__ float snake_u(float u) {
    return fmaf(0.25f, u, fmaf(-0.5f, __cosf(u), 0.5f));
}

__device__ __forceinline__ uint32_t h2u(__half2 v) { return *(uint32_t*)&v; }

// ============================================================================
// Kernel 1: transpose grid [16,64,64,64] f32 -> [64^3][16] f16 (32B/voxel)
// ============================================================================
__global__ void transpose_grid_kernel(const float* __restrict__ g) {
    int v = blockIdx.x * blockDim.x + threadIdx.x;
    if (v >= GRID3) return;
    __half2 h0 = __floats2half2_rn(__ldg(&g[0*GRID3+v]),  __ldg(&g[1*GRID3+v]));
    __half2 h1 = __floats2half2_rn(__ldg(&g[2*GRID3+v]),  __ldg(&g[3*GRID3+v]));
    __half2 h2 = __floats2half2_rn(__ldg(&g[4*GRID3+v]),  __ldg(&g[5*GRID3+v]));
    __half2 h3 = __floats2half2_rn(__ldg(&g[6*GRID3+v]),  __ldg(&g[7*GRID3+v]));
    __half2 h4 = __floats2half2_rn(__ldg(&g[8*GRID3+v]),  __ldg(&g[9*GRID3+v]));
    __half2 h5 = __floats2half2_rn(__ldg(&g[10*GRID3+v]), __ldg(&g[11*GRID3+v]));
    __half2 h6 = __floats2half2_rn(__ldg(&g[12*GRID3+v]), __ldg(&g[13*GRID3+v]));
    __half2 h7 = __floats2half2_rn(__ldg(&g[14*GRID3+v]), __ldg(&g[15*GRID3+v]));
    uint4* dst = (uint4*)&g_gridT[(size_t)v * 16];
    uint4 o0, o1;
    o0.x = h2u(h0); o0.y = h2u(h1); o0.z = h2u(h2); o0.w = h2u(h3);
    o1.x = h2u(h4); o1.y = h2u(h5); o1.z = h2u(h6); o1.w = h2u(h7);
    dst[0] = o0; dst[1] = o1;
}

// ============================================================================
// Pipelined hidden layer (single m-tile of 16 points), depth-2 B prefetch,
// acc parity-double-buffered.
// ============================================================================
__device__ __forceinline__ void hidden_layer(
    const uint32_t (&Ain)[8][4], uint32_t (&Aout)[8][4],
    uint32_t whB, const float* __restrict__ bias, int cb,
    const uint32_t (&Cw)[8])
{
    float acc[2][2][4];                  // [parity][n][4]
#pragma unroll
    for (int t = 0; t < 9; ++t) {
        if (t < 8) {
            const int pb = t & 1;
            float2 b0 = *(const float2*)(bias + 16 * t + cb);
            float2 b1 = *(const float2*)(bias + 16 * t + 8 + cb);
            acc[pb][0][0] = b0.x; acc[pb][0][1] = b0.y;
            acc[pb][0][2] = b0.x; acc[pb][0][3] = b0.y;
            acc[pb][1][0] = b1.x; acc[pb][1][1] = b1.y;
            acc[pb][1][2] = b1.x; acc[pb][1][3] = b1.y;
            const uint32_t rowB = whB + (uint32_t)(t * 4096);
            uint32_t bb[2][4];
            ldsm4(bb[0], rowB + Cw[0]);
            ldsm4(bb[1], rowB + Cw[1]);
#pragma unroll
            for (int kt = 0; kt < 8; ++kt) {
                const uint32_t* b = bb[kt & 1];
                mma16816(acc[pb][0], Ain[kt], b[0], b[2]);
                mma16816(acc[pb][1], Ain[kt], b[1], b[3]);
                if (kt < 6) ldsm4(bb[kt & 1], rowB + Cw[kt + 2]);
            }
        }
        if (t > 0) {
            const int pp = (t - 1) & 1;
            const int tp = t - 1;
            Aout[tp][0] = pack_h2(snake_u(acc[pp][0][0]), snake_u(acc[pp][0][1]));
            Aout[tp][1] = pack_h2(snake_u(acc[pp][0][2]), snake_u(acc[pp][0][3]));
            Aout[tp][2] = pack_h2(snake_u(acc[pp][1][0]), snake_u(acc[pp][1][1]));
            Aout[tp][3] = pack_h2(snake_u(acc[pp][1][2]), snake_u(acc[pp][1][3]));
        }
    }
}

// ============================================================================
// Kernel 2: fused fVSRN — persistent, 13 independent warps per CTA,
// 16 points (one m-tile) per warp-tile.
// ============================================================================
__global__ void __launch_bounds__(THREADS, 1)
fvsrn_kernel(const float* __restrict__ xin,
             const float* __restrict__ W0g,
             const float* __restrict__ b0g,
             const float* __restrict__ Whg,
             const float* __restrict__ bhg,
             const float* __restrict__ Woutg,
             const float* __restrict__ boutg,
             float* __restrict__ out,
             int Npts)
{
    extern __shared__ char smem[];
    const uint32_t sb = smem_u32(smem);
    const int tid = threadIdx.x;

    // ---- one-time weight conversion fp32 -> swizzled fp16 SMEM (2x scaled) --
    for (int idx = tid; idx < 128 * 64; idx += THREADS) {
        int n = idx >> 6, k = idx & 63;
        float v = (k < DIN) ? W0g[n * DIN + k] : (k == DIN ? b0g[n] : 0.0f);
        int c = k >> 3, w = k & 7;
        *(__half*)(smem + OFF_W0 + n * 128 + ((c ^ (n & 7)) << 4) + w * 2) =
            __float2half_rn(2.0f * v);
    }
    for (int idx = tid; idx < 3 * 128 * 128; idx += THREADS) {
        int l = idx >> 14, r = idx & 16383;
        int n = r >> 7, k = r & 127;
        int c = k >> 3, w = k & 7;
        int sw = (c & 8) | ((c ^ n) & 7);
        *(__half*)(smem + OFF_WH + l * 32768 + n * 256 + (sw << 4) + w * 2) =
            __float2half_rn(2.0f * Whg[idx]);
    }
    {
        float* bh = (float*)(smem + OFF_BH);
        float* wo = (float*)(smem + OFF_WOUT);
        for (int i = tid; i < 128; i += THREADS) {
            bh[i]       = 2.0f * bhg[i];
            bh[128 + i] = 2.0f * bhg[128 + i];
            bh[256 + i] = 2.0f * bhg[256 + i];
            wo[i]       = Woutg[i];
        }
        if (tid == 0) *(float*)(smem + OFF_BOUT) = boutg[0];
    }
    __syncthreads();

    const int lane = tid & 31, warp = tid >> 5;
    const uint32_t stage = sb + OFF_STAGE + warp * 2048;
    const uint32_t w0B = sb + OFF_W0;
    const uint32_t whB0 = sb + OFF_WH;
    const uint32_t whB1 = sb + OFF_WH + 32768;
    const uint32_t whB2 = sb + OFF_WH + 65536;
    const float* bh = (const float*)(smem + OFF_BH);
    const float* wo = (const float*)(smem + OFF_WOUT);
    const float boutv = *(const float*)(smem + OFF_BOUT);

    const int nr0 = (lane & 7) + ((lane >> 3) & 1) * 8;
    const int kg  = lane >> 4;
    const int cb  = 2 * (lane & 3);
    const int myrow = lane & 15;           // point row this lane featurizes

    // ---- per-thread ldmatrix address constants (swizzle is t-invariant) ----
    uint32_t Cw[8];   // hidden layers, 256B pitch
    uint32_t C0[4];   // W0 / staging, 128B pitch
#pragma unroll
    for (int kt = 0; kt < 8; ++kt) {
        int kc = 2 * kt + kg;
        Cw[kt] = (uint32_t)(nr0 * 256 + (((kc & 8) | ((kc ^ nr0) & 7)) << 4));
    }
#pragma unroll
    for (int kt = 0; kt < 4; ++kt) {
        int kc = 2 * kt + kg;
        C0[kt] = (uint32_t)(nr0 * 128 + (((kc ^ nr0) & 7) << 4));
    }

    const int nwt = (Npts + 15) >> 4;      // warp-tiles of 16 points
    const int stride = NSM * WARPS;
    int wt0 = blockIdx.x * WARPS + warp;

    // prefetch first tile's coords (both lane halves fetch the same point)
    float cx = 0.0f, cy = 0.0f, cz = 0.0f;
    if (wt0 < nwt) {
        int p0 = wt0 * 16 + myrow;
        if (p0 < Npts) {
            cx = __ldg(&xin[3 * p0 + 0]);
            cy = __ldg(&xin[3 * p0 + 1]);
            cz = __ldg(&xin[3 * p0 + 2]);
        }
    }

    for (int wt = wt0; wt < nwt; wt += stride) {
        const int p = wt * 16 + myrow;
        const float px = cx, py = cy, pz = cz;

        // ---- prefetch next tile's coords ----
        {
            int wtn = wt + stride;
            cx = cy = cz = 0.0f;
            if (wtn < nwt) {
                int pn = wtn * 16 + myrow;
                if (pn < Npts) {
                    cx = __ldg(&xin[3 * pn + 0]);
                    cy = __ldg(&xin[3 * pn + 1]);
                    cz = __ldg(&xin[3 * pn + 2]);
                }
            }
        }

        // ---------------- featurize own point ----------------
        float feat[DIN];
#pragma unroll
        for (int i = 0; i < DIN; ++i) feat[i] = 0.0f;

        if (p < Npts) {
            // --- grid-sample: compute indices and ISSUE all loads first ---
            float fx = (px + 1.0f) * 31.5f;
            float fy = (py + 1.0f) * 31.5f;
            float fz = (pz + 1.0f) * 31.5f;
            int x0 = (int)floorf(fx); x0 = min(max(x0, 0), 63);
            int y0 = (int)floorf(fy); y0 = min(max(y0, 0), 63);
            int z0 = (int)floorf(fz); z0 = min(max(z0, 0), 63);
            int x1 = min(x0 + 1, 63), y1 = min(y0 + 1, 63), z1 = min(z0 + 1, 63);
            float wx1 = fx - x0, wy1 = fy - y0, wz1 = fz - z0;
            int   ix[2] = {x0, x1}, iy[2] = {y0, y1}, iz[2] = {z0, z1};
            float wx[2] = {1.0f - wx1, wx1}, wy[2] = {1.0f - wy1, wy1},
                  wz[2] = {1.0f - wz1, wz1};

            uint4 q[8][2];
            float tw[8];
#pragma unroll
            for (int dz = 0; dz < 2; ++dz)
#pragma unroll
            for (int dy = 0; dy < 2; ++dy)
#pragma unroll
            for (int dx = 0; dx < 2; ++dx) {
                int idx = dz * 4 + dy * 2 + dx;
                tw[idx] = wz[dz] * wy[dy] * wx[dx];
                const uint4* cp = (const uint4*)
                    &g_gridT[(size_t)(((iz[dz] << 6) + iy[dy]) << 6 | ix[dx]) * 16];
                q[idx][0] = __ldg(cp);
                q[idx][1] = __ldg(cp + 1);
            }

            // --- PE while the grid loads are in flight ---
            float s0, c0, s1, c1, s2, c2;
            const float PI = 3.14159265358979f;
            __sincosf(PI * px, &s0, &c0);
            __sincosf(PI * py, &s1, &c1);
            __sincosf(PI * pz, &s2, &c2);
#pragma unroll
            for (int l = 0; l < 6; ++l) {
                feat[6 * l + 0] = s0; feat[6 * l + 1] = s1; feat[6 * l + 2] = s2;
                feat[6 * l + 3] = c0; feat[6 * l + 4] = c1; feat[6 * l + 5] = c2;
                if (l < 5) {
                    float ns0 = 2.0f * s0 * c0, nc0 = fmaf(c0, c0, -s0 * s0);
                    float ns1 = 2.0f * s1 * c1, nc1 = fmaf(c1, c1, -s1 * s1);
                    float ns2 = 2.0f * s2 * c2, nc2 = fmaf(c2, c2, -s2 * s2);
                    s0 = ns0; c0 = nc0; s1 = ns1; c1 = nc1; s2 = ns2; c2 = nc2;
                }
            }

            // --- accumulate the 8 taps ---
            float f[16];
#pragma unroll
            for (int i = 0; i < 16; ++i) f[i] = 0.0f;
#pragma unroll
            for (int idx = 0; idx < 8; ++idx) {
                float w = tw[idx];
                const uint32_t qq[8] = {q[idx][0].x, q[idx][0].y, q[idx][0].z,
                                        q[idx][0].w, q[idx][1].x, q[idx][1].y,
                                        q[idx][1].z, q[idx][1].w};
#pragma unroll
                for (int j = 0; j < 8; ++j) {
                    float2 u = __half22float2(*(const __half2*)&qq[j]);
                    f[2 * j]     = fmaf(w, u.x, f[2 * j]);
                    f[2 * j + 1] = fmaf(w, u.y, f[2 * j + 1]);
                }
            }
#pragma unroll
            for (int i = 0; i < 16; ++i) feat[36 + i] = f[i];
        }

        // pack + stage (only lanes 0-15 store their row; 128B pitch, swizzled)
        if (lane < 16) {
            uint32_t aw[32];
#pragma unroll
            for (int j = 0; j < 26; ++j) aw[j] = pack_h2(feat[2 * j], feat[2 * j + 1]);
            aw[26] = pack_h2(1.0f, 0.0f);      // feature 52 = 1.0 (carries b0)
#pragma unroll
            for (int j = 27; j < 32; ++j) aw[j] = 0u;
#pragma unroll
            for (int c = 0; c < 8; ++c) {
                uint32_t ad = stage + myrow * 128 + ((c ^ (myrow & 7)) << 4);
                asm volatile("st.shared.v4.b32 [%0],{%1,%2,%3,%4};"
                             :: "r"(ad), "r"(aw[4 * c]), "r"(aw[4 * c + 1]),
                                "r"(aw[4 * c + 2]), "r"(aw[4 * c + 3]));
            }
        }
        __syncwarp();

        // ldmatrix A0 frags: 4 k-tiles (K=64)
        uint32_t A0[4][4];
#pragma unroll
        for (int kt = 0; kt < 4; ++kt)
            ldsm4(A0[kt], stage + C0[kt]);

        // ---------------- layer 0 (K=64, bias in weights), pipelined ----------
        uint32_t A1[8][4];
        {
            float acc[2][2][4];
#pragma unroll
            for (int t = 0; t < 9; ++t) {
                if (t < 8) {
                    const int pb = t & 1;
#pragma unroll
                    for (int n = 0; n < 2; ++n)
#pragma unroll
                    for (int j = 0; j < 4; ++j) acc[pb][n][j] = 0.0f;
                    const uint32_t rowB = w0B + (uint32_t)(t * 2048);
                    uint32_t bb[2][4];
                    ldsm4(bb[0], rowB + C0[0]);
                    ldsm4(bb[1], rowB + C0[1]);
#pragma unroll
                    for (int kt = 0; kt < 4; ++kt) {
                        const uint32_t* b = bb[kt & 1];
                        mma16816(acc[pb][0], A0[kt], b[0], b[2]);
                        mma16816(acc[pb][1], A0[kt], b[1], b[3]);
                        if (kt < 2) ldsm4(bb[kt & 1], rowB + C0[kt + 2]);
                    }
                }
                if (t > 0) {
                    const int pp = (t - 1) & 1;
                    const int tp = t - 1;
                    A1[tp][0] = pack_h2(snake_u(acc[pp][0][0]), snake_u(acc[pp][0][1]));
                    A1[tp][1] = pack_h2(snake_u(acc[pp][0][2]), snake_u(acc[pp][0][3]));
                    A1[tp][2] = pack_h2(snake_u(acc[pp][1][0]), snake_u(acc[pp][1][1]));
                    A1[tp][3] = pack_h2(snake_u(acc[pp][1][2]), snake_u(acc[pp][1][3]));
                }
            }
        }

        // ---------------- hidden layers 1, 2 (pipelined, depth-2) ----------
        uint32_t A2[8][4];
        hidden_layer(A1, A2, whB0, bh, cb, Cw);
        uint32_t A3[8][4];
        hidden_layer(A2, A3, whB1, bh + 128, cb, Cw);

        // ---------------- layer 3 + output dot, pipelined ----------------
        float part[2] = {0.0f, 0.0f};
        const float* bh2 = bh + 256;
        {
            float acc[2][2][4];
#pragma unroll
            for (int t = 0; t < 9; ++t) {
                if (t < 8) {
                    const int pb = t & 1;
                    float2 b0 = *(const float2*)(bh2 + 16 * t + cb);
                    float2 b1 = *(const float2*)(bh2 + 16 * t + 8 + cb);
                    acc[pb][0][0] = b0.x; acc[pb][0][1] = b0.y;
                    acc[pb][0][2] = b0.x; acc[pb][0][3] = b0.y;
                    acc[pb][1][0] = b1.x; acc[pb][1][1] = b1.y;
                    acc[pb][1][2] = b1.x; acc[pb][1][3] = b1.y;
                    const uint32_t rowB = whB2 + (uint32_t)(t * 4096);
                    uint32_t bb[2][4];
                    ldsm4(bb[0], rowB + Cw[0]);
                    ldsm4(bb[1], rowB + Cw[1]);
#pragma unroll
                    for (int kt = 0; kt < 8; ++kt) {
                        const uint32_t* b = bb[kt & 1];
                        mma16816(acc[pb][0], A3[kt], b[0], b[2]);
                        mma16816(acc[pb][1], A3[kt], b[1], b[3]);
                        if (kt < 6) ldsm4(bb[kt & 1], rowB + Cw[kt + 2]);
                    }
                }
                if (t > 0) {
                    const int pp = (t - 1) & 1;
                    const int tp = t - 1;
                    float2 w0 = *(const float2*)(wo + 16 * tp + cb);
                    float2 w1 = *(const float2*)(wo + 16 * tp + 8 + cb);
                    part[0] = fmaf(snake_u(acc[pp][0][0]), w0.x, part[0]);
                    part[0] = fmaf(snake_u(acc[pp][0][1]), w0.y, part[0]);
                    part[0] = fmaf(snake_u(acc[pp][1][0]), w1.x, part[0]);
                    part[0] = fmaf(snake_u(acc[pp][1][1]), w1.y, part[0]);
                    part[1] = fmaf(snake_u(acc[pp][0][2]), w0.x, part[1]);
                    part[1] = fmaf(snake_u(acc[pp][0][3]), w0.y, part[1]);
                    part[1] = fmaf(snake_u(acc[pp][1][2]), w1.x, part[1]);
                    part[1] = fmaf(snake_u(acc[pp][1][3]), w1.y, part[1]);
                }
            }
        }
#pragma unroll
        for (int i = 0; i < 2; ++i) {
            part[i] += __shfl_xor_sync(0xffffffffu, part[i], 1);
            part[i] += __shfl_xor_sync(0xffffffffu, part[i], 2);
        }
        if ((lane & 3) == 0) {
            int r = lane >> 2, pb = wt * 16;
            if (pb + r     < Npts) out[pb + r]     = part[0] + boutv;
            if (pb + r + 8 < Npts) out[pb + r + 8] = part[1] + boutv;
        }
    }
}

// ============================================================================
// Launch
// ============================================================================
extern "C" void kernel_launch(void* const* d_in, const int* in_sizes, int n_in,
                              void* d_out, int out_size) {
    const float* x    = (const float*)d_in[0];
    const float* grid = (const float*)d_in[1];
    const float* W0   = (const float*)d_in[2];
    const float* b0   = (const float*)d_in[3];
    const float* Wh   = (const float*)d_in[4];
    const float* bh   = (const float*)d_in[5];
    const float* Wout = (const float*)d_in[6];
    const float* bout = (const float*)d_in[7];
    float* out = (float*)d_out;
    int Npts = in_sizes[0] / 3;

    static int attr_set = 0;
    if (!attr_set) {
        cudaFuncSetAttribute(fvsrn_kernel,
                             cudaFuncAttributeMaxDynamicSharedMemorySize,
                             SMEM_TOTAL);
        attr_set = 1;
    }

    transpose_grid_kernel<<<(GRID3 + 255) / 256, 256>>>(grid);
    fvsrn_kernel<<<NSM, THREADS, SMEM_TOTAL>>>(x, W0, b0, Wh, bh, Wout, bout,
                                               out, Npts);
}

// round 17
// speedup vs baseline: 1.2270x; 1.2270x over previous
// R17: R12 (tile-pair featurize, P=16 MLP halves) at 384 threads / 12 warps
//      (the spill-free operating point; R12@448 spilled to 128 regs).
#include <cuda_runtime.h>
#include <cuda_fp16.h>
#include <cstdint>

// ============================================================================
// Constants
// ============================================================================
#define NSM       148
#define THREADS   384
#define WARPS     12
#define GRID3     262144        // 64^3
#define DIN       52

// SMEM byte offsets
#define OFF_W0    0             // 128 rows * 128B                 = 16384
#define OFF_WH    16384         // 3 * (128 rows * 256B) = 98304   -> 114688
#define OFF_STAGE 114688        // 12 warps * 4096B                -> 163840
#define OFF_BH    163840        // 3*128 f32 = 1536                -> 165376
#define OFF_WOUT  165376        // 128 f32 = 512                   -> 165888
#define OFF_BOUT  165888        // 1 f32
#define SMEM_TOTAL 165892       // <= 232448

// fp16 feature grid, transposed: [64^3 voxels][16 channels]
__device__ __half g_gridT[(size_t)GRID3 * 16];

// ============================================================================
// Helpers (sm_80-era instructions only; PTX target is plain sm_100)
// ============================================================================
__device__ __forceinline__ uint32_t smem_u32(const void* p) {
    uint32_t a;
    asm("{ .reg .u64 t; cvta.to.shared.u64 t, %1; cvt.u32.u64 %0, t; }"
        : "=r"(a) : "l"(p));
    return a;
}

__device__ __forceinline__ void ldsm4(uint32_t* r, uint32_t addr) {
    asm volatile("ldmatrix.sync.aligned.m8n8.x4.shared.b16 {%0,%1,%2,%3},[%4];"
                 : "=r"(r[0]), "=r"(r[1]), "=r"(r[2]), "=r"(r[3]) : "r"(addr));
}

__device__ __forceinline__ void mma16816(float* c, const uint32_t* a,
                                         uint32_t b0, uint32_t b1) {
    asm volatile(
        "mma.sync.aligned.m16n8k16.row.col.f32.f16.f16.f32 "
        "{%0,%1,%2,%3},{%4,%5,%6,%7},{%8,%9},{%0,%1,%2,%3};"
        : "+f"(c[0]), "+f"(c[1]), "+f"(c[2]), "+f"(c[3])
        : "r"(a[0]), "r"(a[1]), "r"(a[2]), "r"(a[3]), "r"(b0), "r"(b1));
}

__device__ __forceinline__ uint32_t pack_h2(float lo, float hi) {
    uint32_t r;
    asm("cvt.rn.f16x2.f32 %0, %1, %2;" : "=r"(r) : "f"(hi), "f"(lo));
    return r;
}

// Weights/biases of snake layers pre-scaled by 2, so GEMM emits u = 2v
// exactly; snake(v) = 0.25u + 0.5 - 0.5*cos(u).
__device__ __forceinline__ float snake_u(float u) {
    return fmaf(0.25f, u, fmaf(-0.5f, __cosf(u), 0.5f));
}

__device__ __forceinline__ uint32_t h2u(__half2 v) { return *(uint32_t*)&v; }

// ============================================================================
// Kernel 1: transpose grid [16,64,64,64] f32 -> [64^3][16] f16 (32B/voxel)
// ============================================================================
__global__ void transpose_grid_kernel(const float* __restrict__ g) {
    int v = blockIdx.x * blockDim.x + threadIdx.x;
    if (v >= GRID3) return;
    __half2 h0 = __floats2half2_rn(__ldg(&g[0*GRID3+v]),  __ldg(&g[1*GRID3+v]));
    __half2 h1 = __floats2half2_rn(__ldg(&g[2*GRID3+v]),  __ldg(&g[3*GRID3+v]));
    __half2 h2 = __floats2half2_rn(__ldg(&g[4*GRID3+v]),  __ldg(&g[5*GRID3+v]));
    __half2 h3 = __floats2half2_rn(__ldg(&g[6*GRID3+v]),  __ldg(&g[7*GRID3+v]));
    __half2 h4 = __floats2half2_rn(__ldg(&g[8*GRID3+v]),  __ldg(&g[9*GRID3+v]));
    __half2 h5 = __floats2half2_rn(__ldg(&g[10*GRID3+v]), __ldg(&g[11*GRID3+v]));
    __half2 h6 = __floats2half2_rn(__ldg(&g[12*GRID3+v]), __ldg(&g[13*GRID3+v]));
    __half2 h7 = __floats2half2_rn(__ldg(&g[14*GRID3+v]), __ldg(&g[15*GRID3+v]));
    uint4* dst = (uint4*)&g_gridT[(size_t)v * 16];
    uint4 o0, o1;
    o0.x = h2u(h0); o0.y = h2u(h1); o0.z = h2u(h2); o0.w = h2u(h3);
    o1.x = h2u(h4); o1.y = h2u(h5); o1.z = h2u(h6); o1.w = h2u(h7);
    dst[0] = o0; dst[1] = o1;
}

// ============================================================================
// Pipelined hidden layer (single m-tile of 16 points):
// B-frag double-buffered ldsm; acc parity-double-buffered so MMA(t) overlaps
// epilogue(t-1). Addresses = base + t*4096 + per-thread constants Cw[kt].
// ============================================================================
__device__ __forceinline__ void hidden_layer(
    const uint32_t (&Ain)[8][4], uint32_t (&Aout)[8][4],
    uint32_t whB, const float* __restrict__ bias, int cb,
    const uint32_t (&Cw)[8])
{
    float acc[2][2][4];                  // [parity][n][4]
#pragma unroll
    for (int t = 0; t < 9; ++t) {
        if (t < 8) {
            const int pb = t & 1;
            float2 b0 = *(const float2*)(bias + 16 * t + cb);
            float2 b1 = *(const float2*)(bias + 16 * t + 8 + cb);
            acc[pb][0][0] = b0.x; acc[pb][0][1] = b0.y;
            acc[pb][0][2] = b0.x; acc[pb][0][3] = b0.y;
            acc[pb][1][0] = b1.x; acc[pb][1][1] = b1.y;
            acc[pb][1][2] = b1.x; acc[pb][1][3] = b1.y;
            const uint32_t rowB = whB + (uint32_t)(t * 4096);
            uint32_t bb[2][4];
            ldsm4(bb[0], rowB + Cw[0]);
#pragma unroll
            for (int kt = 0; kt < 8; ++kt) {
                if (kt < 7) ldsm4(bb[(kt + 1) & 1], rowB + Cw[kt + 1]);
                const uint32_t* b = bb[kt & 1];
                mma16816(acc[pb][0], Ain[kt], b[0], b[2]);
                mma16816(acc[pb][1], Ain[kt], b[1], b[3]);
            }
        }
        if (t > 0) {
            const int pp = (t - 1) & 1;
            const int tp = t - 1;
            Aout[tp][0] = pack_h2(snake_u(acc[pp][0][0]), snake_u(acc[pp][0][1]));
            Aout[tp][1] = pack_h2(snake_u(acc[pp][0][2]), snake_u(acc[pp][0][3]));
            Aout[tp][2] = pack_h2(snake_u(acc[pp][1][0]), snake_u(acc[pp][1][1]));
            Aout[tp][3] = pack_h2(snake_u(acc[pp][1][2]), snake_u(acc[pp][1][3]));
        }
    }
}

// ============================================================================
// Kernel 2: fused fVSRN — persistent, 12 independent warps per CTA.
// Outer loop processes 32 points (all lanes featurize one point each);
// MLP runs twice per group on 16-point halves (P=16 layout, proven R7).
// ============================================================================
__global__ void __launch_bounds__(THREADS, 1)
fvsrn_kernel(const float* __restrict__ xin,
             const float* __restrict__ W0g,
             const float* __restrict__ b0g,
             const float* __restrict__ Whg,
             const float* __restrict__ bhg,
             const float* __restrict__ Woutg,
             const float* __restrict__ boutg,
             float* __restrict__ out,
             int Npts)
{
    extern __shared__ char smem[];
    const uint32_t sb = smem_u32(smem);
    const int tid = threadIdx.x;

    // ---- one-time weight conversion fp32 -> swizzled fp16 SMEM (2x scaled) --
    for (int idx = tid; idx < 128 * 64; idx += THREADS) {
        int n = idx >> 6, k = idx & 63;
        float v = (k < DIN) ? W0g[n * DIN + k] : (k == DIN ? b0g[n] : 0.0f);
        int c = k >> 3, w = k & 7;
        *(__half*)(smem + OFF_W0 + n * 128 + ((c ^ (n & 7)) << 4) + w * 2) =
            __float2half_rn(2.0f * v);
    }
    for (int idx = tid; idx < 3 * 128 * 128; idx += THREADS) {
        int l = idx >> 14, r = idx & 16383;
        int n = r >> 7, k = r & 127;
        int c = k >> 3, w = k & 7;
        int sw = (c & 8) | ((c ^ n) & 7);
        *(__half*)(smem + OFF_WH + l * 32768 + n * 256 + (sw << 4) + w * 2) =
            __float2half_rn(2.0f * Whg[idx]);
    }
    {
        float* bh = (float*)(smem + OFF_BH);
        float* wo = (float*)(smem + OFF_WOUT);
        for (int i = tid; i < 128; i += THREADS) {
            bh[i]       = 2.0f * bhg[i];
            bh[128 + i] = 2.0f * bhg[128 + i];
            bh[256 + i] = 2.0f * bhg[256 + i];
            wo[i]       = Woutg[i];
        }
        if (tid == 0) *(float*)(smem + OFF_BOUT) = boutg[0];
    }
    __syncthreads();

    const int lane = tid & 31, warp = tid >> 5;
    const uint32_t stage = sb + OFF_STAGE + warp * 4096;   // 32 rows x 128B
    const uint32_t w0B = sb + OFF_W0;
    const uint32_t whB0 = sb + OFF_WH;
    const uint32_t whB1 = sb + OFF_WH + 32768;
    const uint32_t whB2 = sb + OFF_WH + 65536;
    const float* bh = (const float*)(smem + OFF_BH);
    const float* wo = (const float*)(smem + OFF_WOUT);
    const float boutv = *(const float*)(smem + OFF_BOUT);

    const int nr0 = (lane & 7) + ((lane >> 3) & 1) * 8;
    const int kg  = lane >> 4;
    const int cb  = 2 * (lane & 3);

    // ---- per-thread ldmatrix address constants (swizzle t-invariant) ----
    uint32_t Cw[8];   // 256B pitch (hidden weights)
    uint32_t C0[4];   // 128B pitch (W0 + stage)
#pragma unroll
    for (int kt = 0; kt < 8; ++kt) {
        int kc = 2 * kt + kg;
        Cw[kt] = (uint32_t)(nr0 * 256 + (((kc & 8) | ((kc ^ nr0) & 7)) << 4));
    }
#pragma unroll
    for (int kt = 0; kt < 4; ++kt) {
        int kc = 2 * kt + kg;
        C0[kt] = (uint32_t)(nr0 * 128 + (((kc ^ nr0) & 7) << 4));
    }

    const int ngrp = (Npts + 31) >> 5;     // groups of 32 points
    const int stride = NSM * WARPS;
    int g0 = blockIdx.x * WARPS + warp;

    float cx = 0.0f, cy = 0.0f, cz = 0.0f;
    if (g0 < ngrp) {
        int p0 = g0 * 32 + lane;
        if (p0 < Npts) {
            cx = __ldg(&xin[3 * p0 + 0]);
            cy = __ldg(&xin[3 * p0 + 1]);
            cz = __ldg(&xin[3 * p0 + 2]);
        }
    }

    for (int grp = g0; grp < ngrp; grp += stride) {
        const int p = grp * 32 + lane;
        const float px = cx, py = cy, pz = cz;

        // ---- prefetch next group's coords ----
        {
            int gn = grp + stride;
            cx = cy = cz = 0.0f;
            if (gn < ngrp) {
                int pn = gn * 32 + lane;
                if (pn < Npts) {
                    cx = __ldg(&xin[3 * pn + 0]);
                    cy = __ldg(&xin[3 * pn + 1]);
                    cz = __ldg(&xin[3 * pn + 2]);
                }
            }
        }

        // ---------------- featurize own point (each lane distinct) ----------
        uint32_t aw[32];
        if (p < Npts) {
            float fx = (px + 1.0f) * 31.5f;
            float fy = (py + 1.0f) * 31.5f;
            float fz = (pz + 1.0f) * 31.5f;
            int x0 = (int)floorf(fx); x0 = min(max(x0, 0), 63);
            int y0 = (int)floorf(fy); y0 = min(max(y0, 0), 63);
            int z0 = (int)floorf(fz); z0 = min(max(z0, 0), 63);
            int x1 = min(x0 + 1, 63), y1 = min(y0 + 1, 63), z1 = min(z0 + 1, 63);
            float wx1 = fx - x0, wy1 = fy - y0, wz1 = fz - z0;
            int   ix[2] = {x0, x1}, iy[2] = {y0, y1}, iz[2] = {z0, z1};
            float wx[2] = {1.0f - wx1, wx1}, wy[2] = {1.0f - wy1, wy1},
                  wz[2] = {1.0f - wz1, wz1};

            float f[16];
#pragma unroll
            for (int i = 0; i < 16; ++i) f[i] = 0.0f;

            // taps in 2 batches of 4 (halves register pressure; MLP=4 hides L2)
#pragma unroll
            for (int half = 0; half < 2; ++half) {
                uint4 qv[4][2];
                float tw[4];
#pragma unroll
                for (int dy = 0; dy < 2; ++dy)
#pragma unroll
                for (int dx = 0; dx < 2; ++dx) {
                    int idx = dy * 2 + dx;
                    tw[idx] = wz[half] * wy[dy] * wx[dx];
                    const uint4* cp = (const uint4*)
                        &g_gridT[(size_t)(((iz[half] << 6) + iy[dy]) << 6 | ix[dx]) * 16];
                    qv[idx][0] = __ldg(cp);
                    qv[idx][1] = __ldg(cp + 1);
                }
                if (half == 0) {
                    // PE while batch-0 loads are in flight
                    float s0, c0, s1, c1, s2, c2;
                    const float PI = 3.14159265358979f;
                    __sincosf(PI * px, &s0, &c0);
                    __sincosf(PI * py, &s1, &c1);
                    __sincosf(PI * pz, &s2, &c2);
#pragma unroll
                    for (int l = 0; l < 6; ++l) {
                        aw[3 * l + 0] = pack_h2(s0, s1);
                        aw[3 * l + 1] = pack_h2(s2, c0);
                        aw[3 * l + 2] = pack_h2(c1, c2);
                        if (l < 5) {
                            float ns0 = 2.0f * s0 * c0, nc0 = fmaf(c0, c0, -s0 * s0);
                            float ns1 = 2.0f * s1 * c1, nc1 = fmaf(c1, c1, -s1 * s1);
                            float ns2 = 2.0f * s2 * c2, nc2 = fmaf(c2, c2, -s2 * s2);
                            s0 = ns0; c0 = nc0; s1 = ns1; c1 = nc1; s2 = ns2; c2 = nc2;
                        }
                    }
                }
#pragma unroll
                for (int idx = 0; idx < 4; ++idx) {
                    float w = tw[idx];
                    const uint32_t qq[8] = {qv[idx][0].x, qv[idx][0].y, qv[idx][0].z,
                                            qv[idx][0].w, qv[idx][1].x, qv[idx][1].y,
                                            qv[idx][1].z, qv[idx][1].w};
#pragma unroll
                    for (int j = 0; j < 8; ++j) {
                        float2 u = __half22float2(*(const __half2*)&qq[j]);
                        f[2 * j]     = fmaf(w, u.x, f[2 * j]);
                        f[2 * j + 1] = fmaf(w, u.y, f[2 * j + 1]);
                    }
                }
            }
#pragma unroll
            for (int j = 0; j < 8; ++j)
                aw[18 + j] = pack_h2(f[2 * j], f[2 * j + 1]);
        } else {
#pragma unroll
            for (int j = 0; j < 26; ++j) aw[j] = 0u;
        }
        aw[26] = pack_h2(1.0f, 0.0f);      // feature 52 = 1.0 (carries b0)
#pragma unroll
        for (int j = 27; j < 32; ++j) aw[j] = 0u;   // padding k=54..63 == 0

        // stage all 32 rows (row = lane, 128B pitch, swizzled)
#pragma unroll
        for (int c = 0; c < 8; ++c) {
            uint32_t ad = stage + lane * 128 + ((c ^ (lane & 7)) << 4);
            asm volatile("st.shared.v4.b32 [%0],{%1,%2,%3,%4};"
                         :: "r"(ad), "r"(aw[4 * c]), "r"(aw[4 * c + 1]),
                            "r"(aw[4 * c + 2]), "r"(aw[4 * c + 3]));
        }
        __syncwarp();

        // ================= MLP twice: halves of the 32-point group ==========
#pragma unroll 1
        for (int hh = 0; hh < 2; ++hh) {
            const uint32_t stH = stage + (uint32_t)(hh * 2048);

            // ldmatrix A0 frags: 4 k-tiles (K=64)
            uint32_t A0[4][4];
#pragma unroll
            for (int kt = 0; kt < 4; ++kt)
                ldsm4(A0[kt], stH + C0[kt]);

            // ---- layer 0 (K=64, bias in weights), pipelined ----
            uint32_t A1[8][4];
            {
                float acc[2][2][4];
#pragma unroll
                for (int t = 0; t < 9; ++t) {
                    if (t < 8) {
                        const int pb = t & 1;
#pragma unroll
                        for (int n = 0; n < 2; ++n)
#pragma unroll
                        for (int j = 0; j < 4; ++j) acc[pb][n][j] = 0.0f;
                        const uint32_t rowB = w0B + (uint32_t)(t * 2048);
                        uint32_t bb[2][4];
                        ldsm4(bb[0], rowB + C0[0]);
#pragma unroll
                        for (int kt = 0; kt < 4; ++kt) {
                            if (kt < 3) ldsm4(bb[(kt + 1) & 1], rowB + C0[kt + 1]);
                            const uint32_t* b = bb[kt & 1];
                            mma16816(acc[pb][0], A0[kt], b[0], b[2]);
                            mma16816(acc[pb][1], A0[kt], b[1], b[3]);
                        }
                    }
                    if (t > 0) {
                        const int pp = (t - 1) & 1;
                        const int tp = t - 1;
                        A1[tp][0] = pack_h2(snake_u(acc[pp][0][0]), snake_u(acc[pp][0][1]));
                        A1[tp][1] = pack_h2(snake_u(acc[pp][0][2]), snake_u(acc[pp][0][3]));
                        A1[tp][2] = pack_h2(snake_u(acc[pp][1][0]), snake_u(acc[pp][1][1]));
                        A1[tp][3] = pack_h2(snake_u(acc[pp][1][2]), snake_u(acc[pp][1][3]));
                    }
                }
            }

            // ---- hidden layers 1, 2 ----
            uint32_t A2[8][4];
            hidden_layer(A1, A2, whB0, bh, cb, Cw);
            uint32_t A3[8][4];
            hidden_layer(A2, A3, whB1, bh + 128, cb, Cw);

            // ---- layer 3 + output dot, pipelined ----
            float part[2] = {0.0f, 0.0f};
            const float* bh2 = bh + 256;
            {
                float acc[2][2][4];
#pragma unroll
                for (int t = 0; t < 9; ++t) {
                    if (t < 8) {
                        const int pb = t & 1;
                        float2 b0 = *(const float2*)(bh2 + 16 * t + cb);
                        float2 b1 = *(const float2*)(bh2 + 16 * t + 8 + cb);
                        acc[pb][0][0] = b0.x; acc[pb][0][1] = b0.y;
                        acc[pb][0][2] = b0.x; acc[pb][0][3] = b0.y;
                        acc[pb][1][0] = b1.x; acc[pb][1][1] = b1.y;
                        acc[pb][1][2] = b1.x; acc[pb][1][3] = b1.y;
                        const uint32_t rowB = whB2 + (uint32_t)(t * 4096);
                        uint32_t bb[2][4];
                        ldsm4(bb[0], rowB + Cw[0]);
#pragma unroll
                        for (int kt = 0; kt < 8; ++kt) {
                            if (kt < 7) ldsm4(bb[(kt + 1) & 1], rowB + Cw[kt + 1]);
                            const uint32_t* b = bb[kt & 1];
                            mma16816(acc[pb][0], A3[kt], b[0], b[2]);
                            mma16816(acc[pb][1], A3[kt], b[1], b[3]);
                        }
                    }
                    if (t > 0) {
                        const int pp = (t - 1) & 1;
                        const int tp = t - 1;
                        float2 w0 = *(const float2*)(wo + 16 * tp + cb);
                        float2 w1 = *(const float2*)(wo + 16 * tp + 8 + cb);
                        part[0] = fmaf(snake_u(acc[pp][0][0]), w0.x, part[0]);
                        part[0] = fmaf(snake_u(acc[pp][0][1]), w0.y, part[0]);
                        part[0] = fmaf(snake_u(acc[pp][1][0]), w1.x, part[0]);
                        part[0] = fmaf(snake_u(acc[pp][1][1]), w1.y, part[0]);
                        part[1] = fmaf(snake_u(acc[pp][0][2]), w0.x, part[1]);
                        part[1] = fmaf(snake_u(acc[pp][0][3]), w0.y, part[1]);
                        part[1] = fmaf(snake_u(acc[pp][1][2]), w1.x, part[1]);
                        part[1] = fmaf(snake_u(acc[pp][1][3]), w1.y, part[1]);
                    }
                }
            }
#pragma unroll
            for (int i = 0; i < 2; ++i) {
                part[i] += __shfl_xor_sync(0xffffffffu, part[i], 1);
                part[i] += __shfl_xor_sync(0xffffffffu, part[i], 2);
            }
            if ((lane & 3) == 0) {
                int r = lane >> 2, pb = grp * 32 + hh * 16;
                if (pb + r     < Npts) out[pb + r]     = part[0] + boutv;
                if (pb + r + 8 < Npts) out[pb + r + 8] = part[1] + boutv;
            }
        }
    }
}

// ============================================================================
// Launch
// ============================================================================
extern "C" void kernel_launch(void* const* d_in, const int* in_sizes, int n_in,
                              void* d_out, int out_size) {
    const float* x    = (const float*)d_in[0];
    const float* grid = (const float*)d_in[1];
    const float* W0   = (const float*)d_in[2];
    const float* b0   = (const float*)d_in[3];
    const float* Wh   = (const float*)d_in[4];
    const float* bh   = (const float*)d_in[5];
    const float* Wout = (const float*)d_in[6];
    const float* bout = (const float*)d_in[7];
    float* out = (float*)d_out;
    int Npts = in_sizes[0] / 3;

    static int attr_set = 0;
    if (!attr_set) {
        cudaFuncSetAttribute(fvsrn_kernel,
                             cudaFuncAttributeMaxDynamicSharedMemorySize,
                             SMEM_TOTAL);
        attr_set = 1;
    }

    transpose_grid_kernel<<<(GRID3 + 255) / 256, 256>>>(grid);
    fvsrn_kernel<<<NSM, THREADS, SMEM_TOTAL>>>(x, W0, b0, Wh, bh, Wout, bout,
                                               out, Npts);
}